// round 2
// baseline (speedup 1.0000x reference)
#include <cuda_runtime.h>

// ---------------------------------------------------------------------------
// WindowAttention (video-swin style, dilated + shifted), fused fp32 kernel.
// B=4, S=8, H=W=112, C=96, HEADS=3, hd=32, WIN=(2,7,7), DIL=(1,2,2), SHIFT=(1,3,3)
// -> 4096 windows of 98 tokens. One CTA per window, 256 threads, ~190KB smem.
// ---------------------------------------------------------------------------

#define WINN 98          // tokens per window
#define CDIM 96          // channels
#define PQ   289         // QKV smem pitch (odd -> conflict-free strided row reads)
#define PW   97          // weight-transpose smem pitch (odd -> conflict-free STS)
#define NT   256
#define NWIN 4096

// Precomputed relative-position bias, layout [head][n][m]
__device__ float g_bias[3 * WINN * WINN];

__global__ void bias_prep_kernel(const float* __restrict__ tbl) {
    int idx = blockIdx.x * blockDim.x + threadIdx.x;
    if (idx >= 3 * WINN * WINN) return;
    int h = idx / (WINN * WINN);
    int r = idx - h * (WINN * WINN);
    int n = r / WINN, m = r - (r / WINN) * WINN;
    int i0n = n / 49, r2n = n - i0n * 49, i1n = r2n / 7, i2n = r2n - i1n * 7;
    int i0m = m / 49, r2m = m - i0m * 49, i1m = r2m / 7, i2m = r2m - i1m * 7;
    int d0 = i0n - i0m + 1;       // 0..2
    int d1 = i1n - i1m + 6;       // 0..12
    int d2 = i2n - i2m + 6;       // 0..12
    int t = (d0 * 13 + d1) * 13 + d2;   // 0..506
    g_bias[idx] = tbl[t * 3 + h];
}

__global__ __launch_bounds__(NT, 1)
void win_attn_kernel(const float* __restrict__ x,
                     const float* __restrict__ qkv_w,
                     const float* __restrict__ qkv_b,
                     const float* __restrict__ proj_w,
                     const float* __restrict__ proj_b,
                     float* __restrict__ out)
{
    extern __shared__ float sm[];
    float* XW  = sm;                         // 98*96   = 9408 (input tile, later attn-out O)
    float* WS  = sm + 9408;                  // 9604: weight^T staging (96*97) / attn buffer (98*98)
    float* ATT = WS;
    float* QKV = sm + 9408 + 9604;           // 98*289  = 28322
    float* RS  = QKV + WINN * PQ;            // 98 softmax inverse-sums
    int*  GOFF = (int*)(RS + WINN);          // 98 token base offsets (elements /96)

    const int tid  = threadIdx.x;
    const int lane = tid & 31;
    const int wgrp = tid >> 5;

    // ---- window decode: dims (B=4, d0=1, d1=2, d2=2, sb=4, hb=8, wb=8) ----
    int widx = blockIdx.x;
    int b   = widx >> 10;
    int rr  = widx & 1023;
    int d1w = (rr >> 9) & 1;
    int d2w = (rr >> 8) & 1;
    int sb  = (rr >> 6) & 3;
    int hb  = (rr >> 3) & 7;
    int wb  =  rr       & 7;

    if (tid < WINN) {
        int n  = tid;
        int i0 = n / 49; int r2 = n - i0 * 49; int i1 = r2 / 7; int i2 = r2 - i1 * 7;
        int s = (sb * 2 + i0 + 1) & 7;                       // roll by tshift=(1,6,6)
        int h = hb * 14 + d1w * 7 + i1 + 6; if (h >= 112) h -= 112;
        int w = wb * 14 + d2w * 7 + i2 + 6; if (w >= 112) w -= 112;
        GOFF[n] = ((b * 8 + s) * 112 + h) * 112 + w;         // token index into (B, S*H*W)
    }
    __syncthreads();

    // ---- load input tile XW[n][c] (gmem-coalesced per token row) ----
    for (int idx = tid; idx < WINN * CDIM; idx += NT) {
        int n = idx / 96, c = idx - n * 96;
        XW[idx] = x[GOFF[n] * 96 + c];
    }
    // covered by the barrier after the first WS load below

    const int m0 = wgrp * 13;                 // each warp owns 13 token rows
    int rbX[13];
    #pragma unroll
    for (int i = 0; i < 13; i++) rbX[i] = min(m0 + i, WINN - 1) * 96;

    const float qscale = 0.17677669529663687f;   // 32^-0.5

    // ================= QKV GEMM: [98,96] x [96,288] in 3 chunks of 96 ==========
    for (int chunk = 0; chunk < 3; chunk++) {
        for (int idx = tid; idx < 96 * 96; idx += NT) {
            int j = idx / 96, kk = idx - j * 96;
            WS[kk * PW + j] = qkv_w[(chunk * 96 + j) * 96 + kk];
        }
        __syncthreads();

        float acc[13][3];
        #pragma unroll
        for (int i = 0; i < 13; i++) { acc[i][0] = 0.f; acc[i][1] = 0.f; acc[i][2] = 0.f; }

        #pragma unroll 4
        for (int kk = 0; kk < 96; kk++) {
            float w0 = WS[kk * PW + lane];
            float w1 = WS[kk * PW + 32 + lane];
            float w2 = WS[kk * PW + 64 + lane];
            #pragma unroll
            for (int i = 0; i < 13; i++) {
                float xv = XW[rbX[i] + kk];
                acc[i][0] += xv * w0;
                acc[i][1] += xv * w1;
                acc[i][2] += xv * w2;
            }
        }
        float b0 = qkv_b[chunk * 96 + lane];
        float b1 = qkv_b[chunk * 96 + 32 + lane];
        float b2 = qkv_b[chunk * 96 + 64 + lane];
        float sc = (chunk == 0) ? qscale : 1.0f;
        #pragma unroll
        for (int i = 0; i < 13; i++) {
            int m = m0 + i;
            if (m < WINN) {
                float* q = QKV + m * PQ + chunk * 96;
                q[lane]      = (acc[i][0] + b0) * sc;
                q[32 + lane] = (acc[i][1] + b1) * sc;
                q[64 + lane] = (acc[i][2] + b2) * sc;
            }
        }
        __syncthreads();
    }

    // ================= Attention per head =====================================
    int rbQ[13], rbA[13];
    #pragma unroll
    for (int i = 0; i < 13; i++) {
        rbQ[i] = min(m0 + i, WINN - 1) * PQ;
        rbA[i] = min(m0 + i, WINN - 1) * WINN;
    }

    for (int h = 0; h < 3; h++) {
        const float* qb = QKV + h * 32;
        const float* kb = QKV + 96 + h * 32;

        // ---- scores: attn[n][m] = q[n].k[m] (q pre-scaled) ----
        float acc[13][4];
        #pragma unroll
        for (int i = 0; i < 13; i++)
            { acc[i][0]=0.f; acc[i][1]=0.f; acc[i][2]=0.f; acc[i][3]=0.f; }

        int mc[4], mcl[4];
        #pragma unroll
        for (int jj = 0; jj < 4; jj++) {
            mc[jj]  = jj * 32 + lane;
            mcl[jj] = min(mc[jj], WINN - 1) * PQ;
        }
        #pragma unroll 4
        for (int d = 0; d < 32; d++) {
            float k0 = kb[mcl[0] + d];
            float k1 = kb[mcl[1] + d];
            float k2 = kb[mcl[2] + d];
            float k3 = kb[mcl[3] + d];
            #pragma unroll
            for (int i = 0; i < 13; i++) {
                float qv = qb[rbQ[i] + d];
                acc[i][0] += qv * k0;
                acc[i][1] += qv * k1;
                acc[i][2] += qv * k2;
                acc[i][3] += qv * k3;
            }
        }
        const float* bt = g_bias + h * (WINN * WINN);
        #pragma unroll
        for (int i = 0; i < 13; i++) {
            int m = m0 + i;
            if (m < WINN) {
                #pragma unroll
                for (int jj = 0; jj < 4; jj++)
                    if (mc[jj] < WINN)
                        ATT[m * WINN + mc[jj]] = acc[i][jj] + bt[m * WINN + mc[jj]];
            }
        }
        __syncthreads();

        // ---- softmax: one warp per row (1/sum folded into AV epilogue) ----
        for (int row = wgrp; row < WINN; row += 8) {
            float mx = -1e30f;
            for (int c = lane; c < WINN; c += 32) mx = fmaxf(mx, ATT[row * WINN + c]);
            #pragma unroll
            for (int o = 16; o; o >>= 1) mx = fmaxf(mx, __shfl_xor_sync(0xffffffffu, mx, o));
            float ssum = 0.f;
            for (int c = lane; c < WINN; c += 32) {
                float e = __expf(ATT[row * WINN + c] - mx);
                ATT[row * WINN + c] = e;
                ssum += e;
            }
            #pragma unroll
            for (int o = 16; o; o >>= 1) ssum += __shfl_xor_sync(0xffffffffu, ssum, o);
            if (lane == 0) RS[row] = 1.0f / ssum;
        }
        __syncthreads();

        // ---- AV: O[n][d] = sum_m attn[n][m] * v[m][d], d = lane ----
        const float* vb = QKV + 192 + h * 32;
        float oacc[13];
        #pragma unroll
        for (int i = 0; i < 13; i++) oacc[i] = 0.f;
        #pragma unroll 2
        for (int m = 0; m < WINN; m++) {
            float vv = vb[m * PQ + lane];
            #pragma unroll
            for (int i = 0; i < 13; i++) oacc[i] += ATT[rbA[i] + m] * vv;
        }
        #pragma unroll
        for (int i = 0; i < 13; i++) {
            int m = m0 + i;
            if (m < WINN) XW[m * 96 + h * 32 + lane] = oacc[i] * RS[m];
        }
        __syncthreads();
    }

    // ================= Projection + scatter-store =============================
    for (int idx = tid; idx < 96 * 96; idx += NT) {
        int j = idx / 96, kk = idx - j * 96;
        WS[kk * PW + j] = proj_w[j * 96 + kk];
    }
    __syncthreads();

    float acc[13][3];
    #pragma unroll
    for (int i = 0; i < 13; i++) { acc[i][0] = 0.f; acc[i][1] = 0.f; acc[i][2] = 0.f; }
    #pragma unroll 4
    for (int kk = 0; kk < 96; kk++) {
        float w0 = WS[kk * PW + lane];
        float w1 = WS[kk * PW + 32 + lane];
        float w2 = WS[kk * PW + 64 + lane];
        #pragma unroll
        for (int i = 0; i < 13; i++) {
            float xv = XW[rbX[i] + kk];
            acc[i][0] += xv * w0;
            acc[i][1] += xv * w1;
            acc[i][2] += xv * w2;
        }
    }
    float p0 = proj_b[lane], p1 = proj_b[32 + lane], p2 = proj_b[64 + lane];
    #pragma unroll
    for (int i = 0; i < 13; i++) {
        int m = m0 + i;
        if (m < WINN) {
            float* o = out + GOFF[m] * 96;
            o[lane]      = acc[i][0] + p0;
            o[32 + lane] = acc[i][1] + p1;
            o[64 + lane] = acc[i][2] + p2;
        }
    }
}

extern "C" void kernel_launch(void* const* d_in, const int* in_sizes, int n_in,
                              void* d_out, int out_size) {
    const float* x      = (const float*)d_in[0];
    const float* qkv_w  = (const float*)d_in[1];
    const float* qkv_b  = (const float*)d_in[2];
    const float* proj_w = (const float*)d_in[3];
    const float* proj_b = (const float*)d_in[4];
    const float* tbl    = (const float*)d_in[5];
    float* out = (float*)d_out;

    // dynamic smem: XW(9408) + WS/ATT(9604) + QKV(28322) + RS(98) floats + GOFF(98 ints)
    const int smem_bytes = (9408 + 9604 + 28322 + 98) * 4 + 98 * 4;   // 190120 B
    cudaFuncSetAttribute(win_attn_kernel,
                         cudaFuncAttributeMaxDynamicSharedMemorySize, smem_bytes);

    // precompute relative bias [3][98][98] (window-invariant)
    bias_prep_kernel<<<(3 * WINN * WINN + 255) / 256, 256>>>(tbl);
    win_attn_kernel<<<NWIN, NT, smem_bytes>>>(x, qkv_w, qkv_b, proj_w, proj_b, out);
}

// round 3
// speedup vs baseline: 1.2142x; 1.2142x over previous
#include <cuda_runtime.h>

// ---------------------------------------------------------------------------
// WindowAttention fused fp32 kernel, v2: packed fma.rn.f32x2 + LDS.128.
// B=4, S=8, H=W=112, C=96, HEADS=3, hd=32, WIN=(2,7,7), DIL=(1,2,2), SHIFT=(1,3,3)
// -> 4096 windows of 98 tokens. One CTA per window, 256 threads, ~188KB smem.
// ---------------------------------------------------------------------------

#define WINN 98          // tokens per window
#define CDIM 96          // channels
#define PQ   292         // QKV smem pitch (4-mult, 292%32=4 -> conflict-free LDS.128)
#define PK   100         // weight smem pitch [j][k]
#define PA   100         // attention-matrix pitch
#define NT   256
#define NWIN 4096

typedef unsigned long long u64;

__device__ __forceinline__ void ffma2(u64& d, u64 a, u64 b) {
    asm("fma.rn.f32x2 %0, %1, %2, %0;" : "+l"(d) : "l"(a), "l"(b));
}
__device__ __forceinline__ u64 pack2(float lo, float hi) {
    u64 r; asm("mov.b64 %0, {%1, %2};" : "=l"(r) : "f"(lo), "f"(hi)); return r;
}
__device__ __forceinline__ float hsum2(u64 v) {
    float a, b; asm("mov.b64 {%0, %1}, %2;" : "=f"(a), "=f"(b) : "l"(v)); return a + b;
}

// Precomputed relative-position bias, layout [head][n][m] (pitch 98)
__device__ float g_bias[3 * WINN * WINN];

__global__ void bias_prep_kernel(const float* __restrict__ tbl) {
    int idx = blockIdx.x * blockDim.x + threadIdx.x;
    if (idx >= 3 * WINN * WINN) return;
    int h = idx / (WINN * WINN);
    int r = idx - h * (WINN * WINN);
    int n = r / WINN, m = r - (r / WINN) * WINN;
    int i0n = n / 49, r2n = n - i0n * 49, i1n = r2n / 7, i2n = r2n - i1n * 7;
    int i0m = m / 49, r2m = m - i0m * 49, i1m = r2m / 7, i2m = r2m - i1m * 7;
    int t = ((i0n - i0m + 1) * 13 + (i1n - i1m + 6)) * 13 + (i2n - i2m + 6);
    g_bias[idx] = tbl[t * 3 + h];
}

__global__ __launch_bounds__(NT, 1)
void win_attn_kernel(const float* __restrict__ x,
                     const float* __restrict__ qkv_w,
                     const float* __restrict__ qkv_b,
                     const float* __restrict__ proj_w,
                     const float* __restrict__ proj_b,
                     float* __restrict__ out)
{
    extern __shared__ float sm[];
    float* XW  = sm;                         // 98*96 = 9408 input tile / attn-out O
    float* WS  = sm + 9408;                  // 9800: weights [96][PK] / ATT [98][PA]
    float* ATT = WS;
    float* QKV = sm + 9408 + 9800;           // 98*292 = 28616
    float* RS  = QKV + WINN * PQ;            // 98 softmax inverse-sums
    int*  GOFF = (int*)(RS + WINN);          // 98 token base offsets

    const int tid  = threadIdx.x;
    const int lane = tid & 31;
    const int wgrp = tid >> 5;

    // ---- window decode ----
    int widx = blockIdx.x;
    int b   = widx >> 10;
    int rr  = widx & 1023;
    int d1w = (rr >> 9) & 1;
    int d2w = (rr >> 8) & 1;
    int sb  = (rr >> 6) & 3;
    int hb  = (rr >> 3) & 7;
    int wb  =  rr       & 7;

    if (tid < WINN) {
        int n  = tid;
        int i0 = n / 49; int r2 = n - i0 * 49; int i1 = r2 / 7; int i2 = r2 - i1 * 7;
        int s = (sb * 2 + i0 + 1) & 7;                       // roll by tshift=(1,6,6)
        int h = hb * 14 + d1w * 7 + i1 + 6; if (h >= 112) h -= 112;
        int w = wb * 14 + d2w * 7 + i2 + 6; if (w >= 112) w -= 112;
        GOFF[n] = ((b * 8 + s) * 112 + h) * 112 + w;
    }
    __syncthreads();

    // ---- load input tile XW[n][c], float4 vectorized ----
    for (int idx = tid; idx < WINN * 24; idx += NT) {
        int n = idx / 24, q = idx - n * 24;
        *(float4*)&XW[n * 96 + q * 4] = *(const float4*)&x[GOFF[n] * 96 + q * 4];
    }
    // barrier after first WS staging below covers this

    const int m0 = wgrp * 13;                 // each warp owns 13 token rows
    int rbX[13];
    #pragma unroll
    for (int i = 0; i < 13; i++) rbX[i] = min(m0 + i, WINN - 1) * 96;

    const float qscale = 0.17677669529663687f;   // 32^-0.5

    // ================= QKV GEMM: [98,96] x [96,288] in 3 chunks =============
    for (int chunk = 0; chunk < 3; chunk++) {
        for (int idx = tid; idx < 96 * 96; idx += NT) {
            int j = idx / 96, kk = idx - j * 96;
            WS[j * PK + kk] = qkv_w[(chunk * 96 + j) * 96 + kk];
        }
        __syncthreads();

        u64 acc[13][3];
        #pragma unroll
        for (int i = 0; i < 13; i++) { acc[i][0] = 0ull; acc[i][1] = 0ull; acc[i][2] = 0ull; }

        const float* w0p = WS + lane * PK;
        const float* w1p = WS + (32 + lane) * PK;
        const float* w2p = WS + (64 + lane) * PK;

        #pragma unroll 2
        for (int k = 0; k < 96; k += 4) {
            ulonglong2 w0 = *(const ulonglong2*)(w0p + k);
            ulonglong2 w1 = *(const ulonglong2*)(w1p + k);
            ulonglong2 w2 = *(const ulonglong2*)(w2p + k);
            #pragma unroll
            for (int i = 0; i < 13; i++) {
                ulonglong2 xv = *(const ulonglong2*)(XW + rbX[i] + k);
                ffma2(acc[i][0], xv.x, w0.x); ffma2(acc[i][0], xv.y, w0.y);
                ffma2(acc[i][1], xv.x, w1.x); ffma2(acc[i][1], xv.y, w1.y);
                ffma2(acc[i][2], xv.x, w2.x); ffma2(acc[i][2], xv.y, w2.y);
            }
        }
        float b0 = qkv_b[chunk * 96 + lane];
        float b1 = qkv_b[chunk * 96 + 32 + lane];
        float b2 = qkv_b[chunk * 96 + 64 + lane];
        float sc = (chunk == 0) ? qscale : 1.0f;
        #pragma unroll
        for (int i = 0; i < 13; i++) {
            int m = m0 + i;
            if (m < WINN) {
                float* q = QKV + m * PQ + chunk * 96;
                q[lane]      = (hsum2(acc[i][0]) + b0) * sc;
                q[32 + lane] = (hsum2(acc[i][1]) + b1) * sc;
                q[64 + lane] = (hsum2(acc[i][2]) + b2) * sc;
            }
        }
        __syncthreads();
    }

    // ================= Attention per head ===================================
    int rbQ[13], rbA[13];
    #pragma unroll
    for (int i = 0; i < 13; i++) {
        rbQ[i] = min(m0 + i, WINN - 1) * PQ;
        rbA[i] = min(m0 + i, WINN - 1) * PA;
    }

    for (int h = 0; h < 3; h++) {
        const float* qb = QKV + h * 32;
        const float* kb = QKV + 96 + h * 32;

        // ---- scores: attn[n][m] = q[n].k[m] (q pre-scaled), packed over d ----
        u64 acc[13][4];
        #pragma unroll
        for (int i = 0; i < 13; i++)
            { acc[i][0]=0ull; acc[i][1]=0ull; acc[i][2]=0ull; acc[i][3]=0ull; }

        int mc[4], mcl[4];
        #pragma unroll
        for (int jj = 0; jj < 4; jj++) {
            mc[jj]  = jj * 32 + lane;
            mcl[jj] = min(mc[jj], WINN - 1) * PQ;
        }
        #pragma unroll 2
        for (int d = 0; d < 32; d += 4) {
            ulonglong2 kv0 = *(const ulonglong2*)(kb + mcl[0] + d);
            ulonglong2 kv1 = *(const ulonglong2*)(kb + mcl[1] + d);
            ulonglong2 kv2 = *(const ulonglong2*)(kb + mcl[2] + d);
            ulonglong2 kv3 = *(const ulonglong2*)(kb + mcl[3] + d);
            #pragma unroll
            for (int i = 0; i < 13; i++) {
                ulonglong2 qv = *(const ulonglong2*)(qb + rbQ[i] + d);
                ffma2(acc[i][0], qv.x, kv0.x); ffma2(acc[i][0], qv.y, kv0.y);
                ffma2(acc[i][1], qv.x, kv1.x); ffma2(acc[i][1], qv.y, kv1.y);
                ffma2(acc[i][2], qv.x, kv2.x); ffma2(acc[i][2], qv.y, kv2.y);
                ffma2(acc[i][3], qv.x, kv3.x); ffma2(acc[i][3], qv.y, kv3.y);
            }
        }
        const float* bt = g_bias + h * (WINN * WINN);
        #pragma unroll
        for (int i = 0; i < 13; i++) {
            int m = m0 + i;
            if (m < WINN) {
                #pragma unroll
                for (int jj = 0; jj < 4; jj++)
                    if (mc[jj] < WINN)
                        ATT[m * PA + mc[jj]] = hsum2(acc[i][jj]) + bt[m * WINN + mc[jj]];
            }
        }
        __syncthreads();

        // ---- softmax: one warp per row (1/sum folded into AV epilogue) ----
        for (int row = wgrp; row < WINN; row += 8) {
            float mx = -1e30f;
            for (int c = lane; c < WINN; c += 32) mx = fmaxf(mx, ATT[row * PA + c]);
            #pragma unroll
            for (int o = 16; o; o >>= 1) mx = fmaxf(mx, __shfl_xor_sync(0xffffffffu, mx, o));
            float ssum = 0.f;
            for (int c = lane; c < WINN; c += 32) {
                float e = __expf(ATT[row * PA + c] - mx);
                ATT[row * PA + c] = e;
                ssum += e;
            }
            #pragma unroll
            for (int o = 16; o; o >>= 1) ssum += __shfl_xor_sync(0xffffffffu, ssum, o);
            if (lane == 0) RS[row] = 1.0f / ssum;
        }
        __syncthreads();

        // ---- AV: O[n][d] = sum_m attn[n][m] * v[m][d], packed over m ----
        const float* vb = QKV + 192 + h * 32;
        u64 oacc[13];
        #pragma unroll
        for (int i = 0; i < 13; i++) oacc[i] = 0ull;

        #pragma unroll 2
        for (int m = 0; m < 96; m += 4) {
            float v0 = vb[(m + 0) * PQ + lane];
            float v1 = vb[(m + 1) * PQ + lane];
            float v2 = vb[(m + 2) * PQ + lane];
            float v3 = vb[(m + 3) * PQ + lane];
            u64 b01 = pack2(v0, v1);
            u64 b23 = pack2(v2, v3);
            #pragma unroll
            for (int i = 0; i < 13; i++) {
                ulonglong2 av = *(const ulonglong2*)(ATT + rbA[i] + m);
                ffma2(oacc[i], av.x, b01);
                ffma2(oacc[i], av.y, b23);
            }
        }
        {   // tail m = 96, 97
            u64 bt2 = pack2(vb[96 * PQ + lane], vb[97 * PQ + lane]);
            #pragma unroll
            for (int i = 0; i < 13; i++) {
                u64 av = *(const u64*)(ATT + rbA[i] + 96);
                ffma2(oacc[i], av, bt2);
            }
        }
        #pragma unroll
        for (int i = 0; i < 13; i++) {
            int m = m0 + i;
            if (m < WINN) XW[m * 96 + h * 32 + lane] = hsum2(oacc[i]) * RS[m];
        }
        __syncthreads();
    }

    // ================= Projection + scatter-store ===========================
    for (int idx = tid; idx < 96 * 96; idx += NT) {
        int j = idx / 96, kk = idx - j * 96;
        WS[j * PK + kk] = proj_w[j * 96 + kk];
    }
    __syncthreads();

    {
        u64 acc[13][3];
        #pragma unroll
        for (int i = 0; i < 13; i++) { acc[i][0] = 0ull; acc[i][1] = 0ull; acc[i][2] = 0ull; }

        const float* w0p = WS + lane * PK;
        const float* w1p = WS + (32 + lane) * PK;
        const float* w2p = WS + (64 + lane) * PK;

        #pragma unroll 2
        for (int k = 0; k < 96; k += 4) {
            ulonglong2 w0 = *(const ulonglong2*)(w0p + k);
            ulonglong2 w1 = *(const ulonglong2*)(w1p + k);
            ulonglong2 w2 = *(const ulonglong2*)(w2p + k);
            #pragma unroll
            for (int i = 0; i < 13; i++) {
                ulonglong2 xv = *(const ulonglong2*)(XW + rbX[i] + k);
                ffma2(acc[i][0], xv.x, w0.x); ffma2(acc[i][0], xv.y, w0.y);
                ffma2(acc[i][1], xv.x, w1.x); ffma2(acc[i][1], xv.y, w1.y);
                ffma2(acc[i][2], xv.x, w2.x); ffma2(acc[i][2], xv.y, w2.y);
            }
        }
        float p0 = proj_b[lane], p1 = proj_b[32 + lane], p2 = proj_b[64 + lane];
        #pragma unroll
        for (int i = 0; i < 13; i++) {
            int m = m0 + i;
            if (m < WINN) {
                float* o = out + GOFF[m] * 96;
                o[lane]      = hsum2(acc[i][0]) + p0;
                o[32 + lane] = hsum2(acc[i][1]) + p1;
                o[64 + lane] = hsum2(acc[i][2]) + p2;
            }
        }
    }
}

extern "C" void kernel_launch(void* const* d_in, const int* in_sizes, int n_in,
                              void* d_out, int out_size) {
    const float* x      = (const float*)d_in[0];
    const float* qkv_w  = (const float*)d_in[1];
    const float* qkv_b  = (const float*)d_in[2];
    const float* proj_w = (const float*)d_in[3];
    const float* proj_b = (const float*)d_in[4];
    const float* tbl    = (const float*)d_in[5];
    float* out = (float*)d_out;

    // smem floats: XW 9408 + WS/ATT 9800 + QKV 28616 + RS 98, plus GOFF 98 ints
    const int smem_bytes = (9408 + 9800 + 28616 + 98) * 4 + 98 * 4;   // 192080 B
    cudaFuncSetAttribute(win_attn_kernel,
                         cudaFuncAttributeMaxDynamicSharedMemorySize, smem_bytes);

    bias_prep_kernel<<<(3 * WINN * WINN + 255) / 256, 256>>>(tbl);
    win_attn_kernel<<<NWIN, NT, smem_bytes>>>(x, qkv_w, qkv_b, proj_w, proj_b, out);
}

// round 4
// speedup vs baseline: 1.2144x; 1.0002x over previous
#include <cuda_runtime.h>

// ---------------------------------------------------------------------------
// WindowAttention fused fp32 kernel, v2: packed fma.rn.f32x2 + LDS.128.
// B=4, S=8, H=W=112, C=96, HEADS=3, hd=32, WIN=(2,7,7), DIL=(1,2,2), SHIFT=(1,3,3)
// -> 4096 windows of 98 tokens. One CTA per window, 256 threads, ~188KB smem.
// ---------------------------------------------------------------------------

#define WINN 98          // tokens per window
#define CDIM 96          // channels
#define PQ   292         // QKV smem pitch (4-mult, 292%32=4 -> conflict-free LDS.128)
#define PK   100         // weight smem pitch [j][k]
#define PA   100         // attention-matrix pitch
#define NT   256
#define NWIN 4096

typedef unsigned long long u64;

__device__ __forceinline__ void ffma2(u64& d, u64 a, u64 b) {
    asm("fma.rn.f32x2 %0, %1, %2, %0;" : "+l"(d) : "l"(a), "l"(b));
}
__device__ __forceinline__ u64 pack2(float lo, float hi) {
    u64 r; asm("mov.b64 %0, {%1, %2};" : "=l"(r) : "f"(lo), "f"(hi)); return r;
}
__device__ __forceinline__ float hsum2(u64 v) {
    float a, b; asm("mov.b64 {%0, %1}, %2;" : "=f"(a), "=f"(b) : "l"(v)); return a + b;
}

// Precomputed relative-position bias, layout [head][n][m] (pitch 98)
__device__ float g_bias[3 * WINN * WINN];

__global__ void bias_prep_kernel(const float* __restrict__ tbl) {
    int idx = blockIdx.x * blockDim.x + threadIdx.x;
    if (idx >= 3 * WINN * WINN) return;
    int h = idx / (WINN * WINN);
    int r = idx - h * (WINN * WINN);
    int n = r / WINN, m = r - (r / WINN) * WINN;
    int i0n = n / 49, r2n = n - i0n * 49, i1n = r2n / 7, i2n = r2n - i1n * 7;
    int i0m = m / 49, r2m = m - i0m * 49, i1m = r2m / 7, i2m = r2m - i1m * 7;
    int t = ((i0n - i0m + 1) * 13 + (i1n - i1m + 6)) * 13 + (i2n - i2m + 6);
    g_bias[idx] = tbl[t * 3 + h];
}

__global__ __launch_bounds__(NT, 1)
void win_attn_kernel(const float* __restrict__ x,
                     const float* __restrict__ qkv_w,
                     const float* __restrict__ qkv_b,
                     const float* __restrict__ proj_w,
                     const float* __restrict__ proj_b,
                     float* __restrict__ out)
{
    extern __shared__ float sm[];
    float* XW  = sm;                         // 98*96 = 9408 input tile / attn-out O
    float* WS  = sm + 9408;                  // 9800: weights [96][PK] / ATT [98][PA]
    float* ATT = WS;
    float* QKV = sm + 9408 + 9800;           // 98*292 = 28616
    float* RS  = QKV + WINN * PQ;            // 98 softmax inverse-sums
    int*  GOFF = (int*)(RS + WINN);          // 98 token base offsets

    const int tid  = threadIdx.x;
    const int lane = tid & 31;
    const int wgrp = tid >> 5;

    // ---- window decode ----
    int widx = blockIdx.x;
    int b   = widx >> 10;
    int rr  = widx & 1023;
    int d1w = (rr >> 9) & 1;
    int d2w = (rr >> 8) & 1;
    int sb  = (rr >> 6) & 3;
    int hb  = (rr >> 3) & 7;
    int wb  =  rr       & 7;

    if (tid < WINN) {
        int n  = tid;
        int i0 = n / 49; int r2 = n - i0 * 49; int i1 = r2 / 7; int i2 = r2 - i1 * 7;
        int s = (sb * 2 + i0 + 1) & 7;                       // roll by tshift=(1,6,6)
        int h = hb * 14 + d1w * 7 + i1 + 6; if (h >= 112) h -= 112;
        int w = wb * 14 + d2w * 7 + i2 + 6; if (w >= 112) w -= 112;
        GOFF[n] = ((b * 8 + s) * 112 + h) * 112 + w;
    }
    __syncthreads();

    // ---- load input tile XW[n][c], float4 vectorized ----
    for (int idx = tid; idx < WINN * 24; idx += NT) {
        int n = idx / 24, q = idx - n * 24;
        *(float4*)&XW[n * 96 + q * 4] = *(const float4*)&x[GOFF[n] * 96 + q * 4];
    }
    // barrier after first WS staging below covers this

    const int m0 = wgrp * 13;                 // each warp owns 13 token rows
    int rbX[13];
    #pragma unroll
    for (int i = 0; i < 13; i++) rbX[i] = min(m0 + i, WINN - 1) * 96;

    const float qscale = 0.17677669529663687f;   // 32^-0.5

    // ================= QKV GEMM: [98,96] x [96,288] in 3 chunks =============
    for (int chunk = 0; chunk < 3; chunk++) {
        for (int idx = tid; idx < 96 * 96; idx += NT) {
            int j = idx / 96, kk = idx - j * 96;
            WS[j * PK + kk] = qkv_w[(chunk * 96 + j) * 96 + kk];
        }
        __syncthreads();

        u64 acc[13][3];
        #pragma unroll
        for (int i = 0; i < 13; i++) { acc[i][0] = 0ull; acc[i][1] = 0ull; acc[i][2] = 0ull; }

        const float* w0p = WS + lane * PK;
        const float* w1p = WS + (32 + lane) * PK;
        const float* w2p = WS + (64 + lane) * PK;

        #pragma unroll 2
        for (int k = 0; k < 96; k += 4) {
            ulonglong2 w0 = *(const ulonglong2*)(w0p + k);
            ulonglong2 w1 = *(const ulonglong2*)(w1p + k);
            ulonglong2 w2 = *(const ulonglong2*)(w2p + k);
            #pragma unroll
            for (int i = 0; i < 13; i++) {
                ulonglong2 xv = *(const ulonglong2*)(XW + rbX[i] + k);
                ffma2(acc[i][0], xv.x, w0.x); ffma2(acc[i][0], xv.y, w0.y);
                ffma2(acc[i][1], xv.x, w1.x); ffma2(acc[i][1], xv.y, w1.y);
                ffma2(acc[i][2], xv.x, w2.x); ffma2(acc[i][2], xv.y, w2.y);
            }
        }
        float b0 = qkv_b[chunk * 96 + lane];
        float b1 = qkv_b[chunk * 96 + 32 + lane];
        float b2 = qkv_b[chunk * 96 + 64 + lane];
        float sc = (chunk == 0) ? qscale : 1.0f;
        #pragma unroll
        for (int i = 0; i < 13; i++) {
            int m = m0 + i;
            if (m < WINN) {
                float* q = QKV + m * PQ + chunk * 96;
                q[lane]      = (hsum2(acc[i][0]) + b0) * sc;
                q[32 + lane] = (hsum2(acc[i][1]) + b1) * sc;
                q[64 + lane] = (hsum2(acc[i][2]) + b2) * sc;
            }
        }
        __syncthreads();
    }

    // ================= Attention per head ===================================
    int rbQ[13], rbA[13];
    #pragma unroll
    for (int i = 0; i < 13; i++) {
        rbQ[i] = min(m0 + i, WINN - 1) * PQ;
        rbA[i] = min(m0 + i, WINN - 1) * PA;
    }

    for (int h = 0; h < 3; h++) {
        const float* qb = QKV + h * 32;
        const float* kb = QKV + 96 + h * 32;

        // ---- scores: attn[n][m] = q[n].k[m] (q pre-scaled), packed over d ----
        u64 acc[13][4];
        #pragma unroll
        for (int i = 0; i < 13; i++)
            { acc[i][0]=0ull; acc[i][1]=0ull; acc[i][2]=0ull; acc[i][3]=0ull; }

        int mc[4], mcl[4];
        #pragma unroll
        for (int jj = 0; jj < 4; jj++) {
            mc[jj]  = jj * 32 + lane;
            mcl[jj] = min(mc[jj], WINN - 1) * PQ;
        }
        #pragma unroll 2
        for (int d = 0; d < 32; d += 4) {
            ulonglong2 kv0 = *(const ulonglong2*)(kb + mcl[0] + d);
            ulonglong2 kv1 = *(const ulonglong2*)(kb + mcl[1] + d);
            ulonglong2 kv2 = *(const ulonglong2*)(kb + mcl[2] + d);
            ulonglong2 kv3 = *(const ulonglong2*)(kb + mcl[3] + d);
            #pragma unroll
            for (int i = 0; i < 13; i++) {
                ulonglong2 qv = *(const ulonglong2*)(qb + rbQ[i] + d);
                ffma2(acc[i][0], qv.x, kv0.x); ffma2(acc[i][0], qv.y, kv0.y);
                ffma2(acc[i][1], qv.x, kv1.x); ffma2(acc[i][1], qv.y, kv1.y);
                ffma2(acc[i][2], qv.x, kv2.x); ffma2(acc[i][2], qv.y, kv2.y);
                ffma2(acc[i][3], qv.x, kv3.x); ffma2(acc[i][3], qv.y, kv3.y);
            }
        }
        const float* bt = g_bias + h * (WINN * WINN);
        #pragma unroll
        for (int i = 0; i < 13; i++) {
            int m = m0 + i;
            if (m < WINN) {
                #pragma unroll
                for (int jj = 0; jj < 4; jj++)
                    if (mc[jj] < WINN)
                        ATT[m * PA + mc[jj]] = hsum2(acc[i][jj]) + bt[m * WINN + mc[jj]];
            }
        }
        __syncthreads();

        // ---- softmax: one warp per row (1/sum folded into AV epilogue) ----
        for (int row = wgrp; row < WINN; row += 8) {
            float mx = -1e30f;
            for (int c = lane; c < WINN; c += 32) mx = fmaxf(mx, ATT[row * PA + c]);
            #pragma unroll
            for (int o = 16; o; o >>= 1) mx = fmaxf(mx, __shfl_xor_sync(0xffffffffu, mx, o));
            float ssum = 0.f;
            for (int c = lane; c < WINN; c += 32) {
                float e = __expf(ATT[row * PA + c] - mx);
                ATT[row * PA + c] = e;
                ssum += e;
            }
            #pragma unroll
            for (int o = 16; o; o >>= 1) ssum += __shfl_xor_sync(0xffffffffu, ssum, o);
            if (lane == 0) RS[row] = 1.0f / ssum;
        }
        __syncthreads();

        // ---- AV: O[n][d] = sum_m attn[n][m] * v[m][d], packed over m ----
        const float* vb = QKV + 192 + h * 32;
        u64 oacc[13];
        #pragma unroll
        for (int i = 0; i < 13; i++) oacc[i] = 0ull;

        #pragma unroll 2
        for (int m = 0; m < 96; m += 4) {
            float v0 = vb[(m + 0) * PQ + lane];
            float v1 = vb[(m + 1) * PQ + lane];
            float v2 = vb[(m + 2) * PQ + lane];
            float v3 = vb[(m + 3) * PQ + lane];
            u64 b01 = pack2(v0, v1);
            u64 b23 = pack2(v2, v3);
            #pragma unroll
            for (int i = 0; i < 13; i++) {
                ulonglong2 av = *(const ulonglong2*)(ATT + rbA[i] + m);
                ffma2(oacc[i], av.x, b01);
                ffma2(oacc[i], av.y, b23);
            }
        }
        {   // tail m = 96, 97
            u64 bt2 = pack2(vb[96 * PQ + lane], vb[97 * PQ + lane]);
            #pragma unroll
            for (int i = 0; i < 13; i++) {
                u64 av = *(const u64*)(ATT + rbA[i] + 96);
                ffma2(oacc[i], av, bt2);
            }
        }
        #pragma unroll
        for (int i = 0; i < 13; i++) {
            int m = m0 + i;
            if (m < WINN) XW[m * 96 + h * 32 + lane] = hsum2(oacc[i]) * RS[m];
        }
        __syncthreads();
    }

    // ================= Projection + scatter-store ===========================
    for (int idx = tid; idx < 96 * 96; idx += NT) {
        int j = idx / 96, kk = idx - j * 96;
        WS[j * PK + kk] = proj_w[j * 96 + kk];
    }
    __syncthreads();

    {
        u64 acc[13][3];
        #pragma unroll
        for (int i = 0; i < 13; i++) { acc[i][0] = 0ull; acc[i][1] = 0ull; acc[i][2] = 0ull; }

        const float* w0p = WS + lane * PK;
        const float* w1p = WS + (32 + lane) * PK;
        const float* w2p = WS + (64 + lane) * PK;

        #pragma unroll 2
        for (int k = 0; k < 96; k += 4) {
            ulonglong2 w0 = *(const ulonglong2*)(w0p + k);
            ulonglong2 w1 = *(const ulonglong2*)(w1p + k);
            ulonglong2 w2 = *(const ulonglong2*)(w2p + k);
            #pragma unroll
            for (int i = 0; i < 13; i++) {
                ulonglong2 xv = *(const ulonglong2*)(XW + rbX[i] + k);
                ffma2(acc[i][0], xv.x, w0.x); ffma2(acc[i][0], xv.y, w0.y);
                ffma2(acc[i][1], xv.x, w1.x); ffma2(acc[i][1], xv.y, w1.y);
                ffma2(acc[i][2], xv.x, w2.x); ffma2(acc[i][2], xv.y, w2.y);
            }
        }
        float p0 = proj_b[lane], p1 = proj_b[32 + lane], p2 = proj_b[64 + lane];
        #pragma unroll
        for (int i = 0; i < 13; i++) {
            int m = m0 + i;
            if (m < WINN) {
                float* o = out + GOFF[m] * 96;
                o[lane]      = hsum2(acc[i][0]) + p0;
                o[32 + lane] = hsum2(acc[i][1]) + p1;
                o[64 + lane] = hsum2(acc[i][2]) + p2;
            }
        }
    }
}

extern "C" void kernel_launch(void* const* d_in, const int* in_sizes, int n_in,
                              void* d_out, int out_size) {
    const float* x      = (const float*)d_in[0];
    const float* qkv_w  = (const float*)d_in[1];
    const float* qkv_b  = (const float*)d_in[2];
    const float* proj_w = (const float*)d_in[3];
    const float* proj_b = (const float*)d_in[4];
    const float* tbl    = (const float*)d_in[5];
    float* out = (float*)d_out;

    // smem floats: XW 9408 + WS/ATT 9800 + QKV 28616 + RS 98, plus GOFF 98 ints
    const int smem_bytes = (9408 + 9800 + 28616 + 98) * 4 + 98 * 4;   // 192080 B
    cudaFuncSetAttribute(win_attn_kernel,
                         cudaFuncAttributeMaxDynamicSharedMemorySize, smem_bytes);

    bias_prep_kernel<<<(3 * WINN * WINN + 255) / 256, 256>>>(tbl);
    win_attn_kernel<<<NWIN, NT, smem_bytes>>>(x, qkv_w, qkv_b, proj_w, proj_b, out);
}